// round 4
// baseline (speedup 1.0000x reference)
#include <cuda_runtime.h>
#include <cstdint>

#define Bx 8
#define Dx 128
#define Tx 4096
#define Kx 1024
#define Sx 8
#define ROWS (Bx*Tx)            // 32768
#define BLK_M 128
#define BLK_N 128
#define NTILES (Kx/BLK_N)       // 8
#define GRID_STAGE (ROWS/BLK_M) // 256

// scratch (device-global; no runtime allocation allowed)
__device__ float g_R[(size_t)ROWS * Dx];       // residual, row-major (row, d)
__device__ float g_Q[(size_t)ROWS * Dx];       // accumulated quantized
__device__ float g_c2[Sx * Kx];                // ||codeword||^2 per stage
__device__ int   g_codes[Sx * ROWS];           // argmin indices
__device__ float g_part[Sx * GRID_STAGE];      // per-CTA commit partial sums

// ---------------------------------------------------------------------------
// Transpose x (B, D, T) -> R (B*T, D); zero Q.
// ---------------------------------------------------------------------------
__global__ void prep_transpose(const float* __restrict__ x) {
    __shared__ float tile[32][33];
    int b  = blockIdx.z;
    int d0 = blockIdx.y * 32;
    int t0 = blockIdx.x * 32;
    int lx = threadIdx.x, ly = threadIdx.y;   // 32 x 8
    #pragma unroll
    for (int yy = ly; yy < 32; yy += 8)
        tile[yy][lx] = x[((size_t)b * Dx + d0 + yy) * Tx + t0 + lx];
    __syncthreads();
    #pragma unroll
    for (int yy = ly; yy < 32; yy += 8) {
        size_t off = ((size_t)b * Tx + t0 + yy) * Dx + d0 + lx;
        g_R[off] = tile[lx][yy];
        g_Q[off] = 0.0f;
    }
}

// ---------------------------------------------------------------------------
// ||c||^2 for all stages: one warp per codeword.
// ---------------------------------------------------------------------------
__global__ void c2_kernel(const float* __restrict__ cb) {
    int w    = (blockIdx.x * blockDim.x + threadIdx.x) >> 5;
    int lane = threadIdx.x & 31;
    if (w >= Sx * Kx) return;
    float4 v = reinterpret_cast<const float4*>(cb)[(size_t)w * 32 + lane];
    float p = v.x * v.x + v.y * v.y + v.z * v.z + v.w * v.w;
    #pragma unroll
    for (int o = 16; o; o >>= 1) p += __shfl_down_sync(0xFFFFFFFFu, p, o);
    if (lane == 0) g_c2[w] = p;
}

// ---------------------------------------------------------------------------
// One RVQ stage: scores = R @ C^T (128x1024x128 per CTA-tile), online argmin of
// (||c||^2 - 2*score), then gather + residual/qout update + commit partial.
// ---------------------------------------------------------------------------
__global__ void __launch_bounds__(256) stage_kernel(const float* __restrict__ cb_all, int s) {
    extern __shared__ float sm[];
    float* As   = sm;                       // [128][132]  (d-major, padded)
    float* Bs   = As + 128 * 132;           // [16][132]
    float* redv = Bs + 16 * 132;            // [2048]
    int*   redi = (int*)(redv + 2048);      // [2048]
    int*   bidx = redi + 2048;              // [128]

    const float* cb = cb_all + (size_t)s * Kx * Dx;
    const int row0 = blockIdx.x * BLK_M;
    const int tid  = threadIdx.x;
    const int tx   = tid & 15;
    const int ty   = tid >> 4;

    // ---- load residual tile into smem, transposed to [d][m] ----
    const float4* R4 = reinterpret_cast<const float4*>(g_R + (size_t)row0 * Dx);
    #pragma unroll
    for (int it = 0; it < (BLK_M * Dx / 4) / 256; it++) {
        int idx = it * 256 + tid;
        int m  = idx >> 5;          // 32 float4 per row
        int d4 = idx & 31;
        float4 v = R4[(size_t)m * 32 + d4];
        As[(d4 * 4 + 0) * 132 + m] = v.x;
        As[(d4 * 4 + 1) * 132 + m] = v.y;
        As[(d4 * 4 + 2) * 132 + m] = v.z;
        As[(d4 * 4 + 3) * 132 + m] = v.w;
    }

    float minv[8];
    int   mini[8];
    #pragma unroll
    for (int i = 0; i < 8; i++) { minv[i] = __int_as_float(0x7F800000); mini[i] = 0; }

    for (int nt = 0; nt < NTILES; nt++) {
        const int n0 = nt * BLK_N;
        float acc[8][8];
        #pragma unroll
        for (int i = 0; i < 8; i++)
            #pragma unroll
            for (int j = 0; j < 8; j++) acc[i][j] = 0.0f;

        for (int kk = 0; kk < Dx / 16; kk++) {
            __syncthreads();   // Bs (and first-iter As) safe to (re)write / first read
            // load codebook chunk [BLK_N][16] -> Bs[d][n]
            #pragma unroll
            for (int it = 0; it < (BLK_N * 16 / 4) / 256; it++) {
                int idx = it * 256 + tid;
                int n  = idx >> 2;
                int d4 = idx & 3;
                float4 v = *reinterpret_cast<const float4*>(
                    cb + (size_t)(n0 + n) * Dx + kk * 16 + d4 * 4);
                Bs[(d4 * 4 + 0) * 132 + n] = v.x;
                Bs[(d4 * 4 + 1) * 132 + n] = v.y;
                Bs[(d4 * 4 + 2) * 132 + n] = v.z;
                Bs[(d4 * 4 + 3) * 132 + n] = v.w;
            }
            __syncthreads();
            #pragma unroll
            for (int k = 0; k < 16; k++) {
                int dd = kk * 16 + k;
                float4 a0 = *reinterpret_cast<const float4*>(&As[dd * 132 + ty * 8]);
                float4 a1 = *reinterpret_cast<const float4*>(&As[dd * 132 + ty * 8 + 4]);
                float4 b0 = *reinterpret_cast<const float4*>(&Bs[k  * 132 + tx * 8]);
                float4 b1 = *reinterpret_cast<const float4*>(&Bs[k  * 132 + tx * 8 + 4]);
                float a[8] = {a0.x, a0.y, a0.z, a0.w, a1.x, a1.y, a1.z, a1.w};
                float b[8] = {b0.x, b0.y, b0.z, b0.w, b1.x, b1.y, b1.z, b1.w};
                #pragma unroll
                for (int i = 0; i < 8; i++)
                    #pragma unroll
                    for (int j = 0; j < 8; j++)
                        acc[i][j] = fmaf(a[i], b[j], acc[i][j]);
            }
        }

        // ---- online argmin of (c2 - 2*score); k ascending => strict '<' keeps first ----
        #pragma unroll
        for (int j = 0; j < 8; j++) {
            int gk = n0 + tx * 8 + j;
            float c2 = g_c2[s * Kx + gk];
            #pragma unroll
            for (int i = 0; i < 8; i++) {
                float v = fmaf(-2.0f, acc[i][j], c2);
                if (v < minv[i]) { minv[i] = v; mini[i] = gk; }
            }
        }
    }

    // ---- cross-thread argmin reduction per row (tie -> smaller index) ----
    __syncthreads();
    #pragma unroll
    for (int i = 0; i < 8; i++) {
        redv[(ty * 8 + i) * 16 + tx] = minv[i];
        redi[(ty * 8 + i) * 16 + tx] = mini[i];
    }
    __syncthreads();
    if (tid < BLK_M) {
        float bv = redv[tid * 16];
        int   bi = redi[tid * 16];
        #pragma unroll
        for (int t = 1; t < 16; t++) {
            float v = redv[tid * 16 + t];
            int   ix = redi[tid * 16 + t];
            if (v < bv || (v == bv && ix < bi)) { bv = v; bi = ix; }
        }
        bidx[tid] = bi;
        g_codes[s * ROWS + row0 + tid] = bi;
    }
    __syncthreads();

    // ---- gather chosen codeword, update residual & qout, commit partial ----
    float commit = 0.0f;
    #pragma unroll
    for (int it = 0; it < (BLK_M * Dx) / 256; it++) {
        int idx = it * 256 + tid;
        int m = idx >> 7;
        int d = idx & 127;
        int k = bidx[m];
        float q = cb[(size_t)k * Dx + d];
        size_t off = (size_t)(row0 + m) * Dx + d;
        float r = g_R[off];
        float df = q - r;
        commit = fmaf(df, df, commit);
        g_R[off] = r - q;
        g_Q[off] += q;
    }
    __syncthreads();           // redv free for reuse
    redv[tid] = commit;
    __syncthreads();
    #pragma unroll
    for (int st = 128; st > 0; st >>= 1) {
        if (tid < st) redv[tid] += redv[tid + st];
        __syncthreads();
    }
    if (tid == 0) g_part[s * GRID_STAGE + blockIdx.x] = redv[0];
}

// ---------------------------------------------------------------------------
// Q (B*T, D) -> out quantized (B, D, T)
// ---------------------------------------------------------------------------
__global__ void finish_transpose(float* __restrict__ out) {
    __shared__ float tile[32][33];
    int b  = blockIdx.z;
    int d0 = blockIdx.y * 32;
    int t0 = blockIdx.x * 32;
    int lx = threadIdx.x, ly = threadIdx.y;
    #pragma unroll
    for (int yy = ly; yy < 32; yy += 8)
        tile[yy][lx] = g_Q[((size_t)b * Tx + t0 + yy) * Dx + d0 + lx];
    __syncthreads();
    #pragma unroll
    for (int yy = ly; yy < 32; yy += 8)
        out[((size_t)b * Dx + d0 + yy) * Tx + t0 + lx] = tile[lx][yy];
}

// ---------------------------------------------------------------------------
// codes -> float, bw, penalty
// ---------------------------------------------------------------------------
__global__ void pack_kernel(float* __restrict__ out) {
    const size_t QOFF = (size_t)Bx * Dx * Tx;       // 4,194,304
    const size_t COFF = QOFF + (size_t)Sx * ROWS;   // + 262,144
    int i = blockIdx.x * 256 + threadIdx.x;
    if (i < Sx * ROWS) out[QOFF + i] = (float)g_codes[i];
    if (i == 0) {
        float ssum = 0.0f;
        for (int j = 0; j < Sx * GRID_STAGE; j++) ssum += g_part[j];
        out[COFF + 0] = 6000.0f;                                    // 8 * log2(1024) * 75
        out[COFF + 1] = ssum / ((float)Sx * (float)ROWS * (float)Dx);
    }
}

extern "C" void kernel_launch(void* const* d_in, const int* in_sizes, int n_in,
                              void* d_out, int out_size) {
    const float* x  = (const float*)d_in[0];
    const float* cb = (const float*)d_in[1];
    float* out = (float*)d_out;

    const int SMEM_BYTES = (128 * 132 + 16 * 132 + 2048 + 2048 + 128) * 4; // 92,928 B
    cudaFuncSetAttribute(stage_kernel, cudaFuncAttributeMaxDynamicSharedMemorySize, SMEM_BYTES);

    prep_transpose<<<dim3(Tx / 32, Dx / 32, Bx), dim3(32, 8)>>>(x);
    c2_kernel<<<(Sx * Kx * 32) / 256, 256>>>(cb);
    for (int s = 0; s < Sx; s++)
        stage_kernel<<<GRID_STAGE, 256, SMEM_BYTES>>>(cb, s);
    finish_transpose<<<dim3(Tx / 32, Dx / 32, Bx), dim3(32, 8)>>>(out);
    pack_kernel<<<(Sx * ROWS + 255) / 256, 256>>>(out);
}

// round 5
// speedup vs baseline: 1.6177x; 1.6177x over previous
#include <cuda_runtime.h>
#include <cstdint>

#define Bx 8
#define Dx 128
#define Tx 4096
#define Kx 1024
#define Sx 8
#define ROWS (Bx*Tx)            // 32768
#define BLK_M 128
#define BLK_N 128
#define NTILES (Kx/BLK_N)       // 8
#define GRID_STAGE (ROWS/BLK_M) // 256

// scratch (device-global; no runtime allocation allowed)
__device__ float g_R[(size_t)ROWS * Dx];       // residual, row-major (row, d)
__device__ float g_Q[(size_t)ROWS * Dx];       // accumulated quantized
__device__ float g_c2[Sx * Kx];                // ||codeword||^2 per stage
__device__ int   g_codes[Sx * ROWS];           // argmin indices
__device__ float g_part[Sx * GRID_STAGE];      // per-CTA commit partial sums

// ---------------------------------------------------------------------------
// Transpose x (B, D, T) -> R (B*T, D); zero Q.
// ---------------------------------------------------------------------------
__global__ void prep_transpose(const float* __restrict__ x) {
    __shared__ float tile[32][33];
    int b  = blockIdx.z;
    int d0 = blockIdx.y * 32;
    int t0 = blockIdx.x * 32;
    int lx = threadIdx.x, ly = threadIdx.y;   // 32 x 8
    #pragma unroll
    for (int yy = ly; yy < 32; yy += 8)
        tile[yy][lx] = x[((size_t)b * Dx + d0 + yy) * Tx + t0 + lx];
    __syncthreads();
    #pragma unroll
    for (int yy = ly; yy < 32; yy += 8) {
        size_t off = ((size_t)b * Tx + t0 + yy) * Dx + d0 + lx;
        g_R[off] = tile[lx][yy];
        g_Q[off] = 0.0f;
    }
}

// ---------------------------------------------------------------------------
// ||c||^2 for all stages: one warp per codeword.
// ---------------------------------------------------------------------------
__global__ void c2_kernel(const float* __restrict__ cb) {
    int w    = (blockIdx.x * blockDim.x + threadIdx.x) >> 5;
    int lane = threadIdx.x & 31;
    if (w >= Sx * Kx) return;
    float4 v = reinterpret_cast<const float4*>(cb)[(size_t)w * 32 + lane];
    float p = v.x * v.x + v.y * v.y + v.z * v.z + v.w * v.w;
    #pragma unroll
    for (int o = 16; o; o >>= 1) p += __shfl_down_sync(0xFFFFFFFFu, p, o);
    if (lane == 0) g_c2[w] = p;
}

// ---------------------------------------------------------------------------
// One RVQ stage: scores = R @ C^T (128x1024x128 per CTA-tile), online argmin of
// (||c||^2 - 2*score), then gather + residual/qout update + commit partial.
// ---------------------------------------------------------------------------
__global__ void __launch_bounds__(256) stage_kernel(const float* __restrict__ cb_all, int s) {
    extern __shared__ float sm[];
    float* As   = sm;                       // [128][132]  (d-major, padded)
    float* Bs   = As + 128 * 132;           // [16][132]
    float* redv = Bs + 16 * 132;            // [2048]
    int*   redi = (int*)(redv + 2048);      // [2048]
    int*   bidx = redi + 2048;              // [128]

    const float* cb = cb_all + (size_t)s * Kx * Dx;
    const int row0 = blockIdx.x * BLK_M;
    const int tid  = threadIdx.x;
    const int tx   = tid & 15;
    const int ty   = tid >> 4;

    // ---- load residual tile into smem, transposed to [d][m] ----
    const float4* R4 = reinterpret_cast<const float4*>(g_R + (size_t)row0 * Dx);
    #pragma unroll
    for (int it = 0; it < (BLK_M * Dx / 4) / 256; it++) {
        int idx = it * 256 + tid;
        int m  = idx >> 5;          // 32 float4 per row
        int d4 = idx & 31;
        float4 v = R4[(size_t)m * 32 + d4];
        As[(d4 * 4 + 0) * 132 + m] = v.x;
        As[(d4 * 4 + 1) * 132 + m] = v.y;
        As[(d4 * 4 + 2) * 132 + m] = v.z;
        As[(d4 * 4 + 3) * 132 + m] = v.w;
    }

    float minv[8];
    int   mini[8];
    #pragma unroll
    for (int i = 0; i < 8; i++) { minv[i] = __int_as_float(0x7F800000); mini[i] = 0; }

    for (int nt = 0; nt < NTILES; nt++) {
        const int n0 = nt * BLK_N;
        float acc[8][8];
        #pragma unroll
        for (int i = 0; i < 8; i++)
            #pragma unroll
            for (int j = 0; j < 8; j++) acc[i][j] = 0.0f;

        for (int kk = 0; kk < Dx / 16; kk++) {
            __syncthreads();   // Bs (and first-iter As) safe to (re)write / first read
            // load codebook chunk [BLK_N][16] -> Bs[d][n]
            #pragma unroll
            for (int it = 0; it < (BLK_N * 16 / 4) / 256; it++) {
                int idx = it * 256 + tid;
                int n  = idx >> 2;
                int d4 = idx & 3;
                float4 v = *reinterpret_cast<const float4*>(
                    cb + (size_t)(n0 + n) * Dx + kk * 16 + d4 * 4);
                Bs[(d4 * 4 + 0) * 132 + n] = v.x;
                Bs[(d4 * 4 + 1) * 132 + n] = v.y;
                Bs[(d4 * 4 + 2) * 132 + n] = v.z;
                Bs[(d4 * 4 + 3) * 132 + n] = v.w;
            }
            __syncthreads();
            #pragma unroll
            for (int k = 0; k < 16; k++) {
                int dd = kk * 16 + k;
                float4 a0 = *reinterpret_cast<const float4*>(&As[dd * 132 + ty * 8]);
                float4 a1 = *reinterpret_cast<const float4*>(&As[dd * 132 + ty * 8 + 4]);
                float4 b0 = *reinterpret_cast<const float4*>(&Bs[k  * 132 + tx * 8]);
                float4 b1 = *reinterpret_cast<const float4*>(&Bs[k  * 132 + tx * 8 + 4]);
                float a[8] = {a0.x, a0.y, a0.z, a0.w, a1.x, a1.y, a1.z, a1.w};
                float b[8] = {b0.x, b0.y, b0.z, b0.w, b1.x, b1.y, b1.z, b1.w};
                #pragma unroll
                for (int i = 0; i < 8; i++)
                    #pragma unroll
                    for (int j = 0; j < 8; j++)
                        acc[i][j] = fmaf(a[i], b[j], acc[i][j]);
            }
        }

        // ---- online argmin of (c2 - 2*score); k ascending => strict '<' keeps first ----
        #pragma unroll
        for (int j = 0; j < 8; j++) {
            int gk = n0 + tx * 8 + j;
            float c2 = g_c2[s * Kx + gk];
            #pragma unroll
            for (int i = 0; i < 8; i++) {
                float v = fmaf(-2.0f, acc[i][j], c2);
                if (v < minv[i]) { minv[i] = v; mini[i] = gk; }
            }
        }
    }

    // ---- cross-thread argmin reduction per row (tie -> smaller index) ----
    __syncthreads();
    #pragma unroll
    for (int i = 0; i < 8; i++) {
        redv[(ty * 8 + i) * 16 + tx] = minv[i];
        redi[(ty * 8 + i) * 16 + tx] = mini[i];
    }
    __syncthreads();
    if (tid < BLK_M) {
        float bv = redv[tid * 16];
        int   bi = redi[tid * 16];
        #pragma unroll
        for (int t = 1; t < 16; t++) {
            float v = redv[tid * 16 + t];
            int   ix = redi[tid * 16 + t];
            if (v < bv || (v == bv && ix < bi)) { bv = v; bi = ix; }
        }
        bidx[tid] = bi;
        g_codes[s * ROWS + row0 + tid] = bi;
    }
    __syncthreads();

    // ---- gather chosen codeword, update residual & qout, commit partial ----
    float commit = 0.0f;
    #pragma unroll
    for (int it = 0; it < (BLK_M * Dx) / 256; it++) {
        int idx = it * 256 + tid;
        int m = idx >> 7;
        int d = idx & 127;
        int k = bidx[m];
        float q = cb[(size_t)k * Dx + d];
        size_t off = (size_t)(row0 + m) * Dx + d;
        float r = g_R[off];
        float df = q - r;
        commit = fmaf(df, df, commit);
        g_R[off] = r - q;
        g_Q[off] += q;
    }
    __syncthreads();           // redv free for reuse
    redv[tid] = commit;
    __syncthreads();
    #pragma unroll
    for (int st = 128; st > 0; st >>= 1) {
        if (tid < st) redv[tid] += redv[tid + st];
        __syncthreads();
    }
    if (tid == 0) g_part[s * GRID_STAGE + blockIdx.x] = redv[0];
}

// ---------------------------------------------------------------------------
// Q (B*T, D) -> out quantized (B, D, T)
// ---------------------------------------------------------------------------
__global__ void finish_transpose(float* __restrict__ out) {
    __shared__ float tile[32][33];
    int b  = blockIdx.z;
    int d0 = blockIdx.y * 32;
    int t0 = blockIdx.x * 32;
    int lx = threadIdx.x, ly = threadIdx.y;
    #pragma unroll
    for (int yy = ly; yy < 32; yy += 8)
        tile[yy][lx] = g_Q[((size_t)b * Tx + t0 + yy) * Dx + d0 + lx];
    __syncthreads();
    #pragma unroll
    for (int yy = ly; yy < 32; yy += 8)
        out[((size_t)b * Dx + d0 + yy) * Tx + t0 + lx] = tile[lx][yy];
}

// ---------------------------------------------------------------------------
// codes -> float, bw, penalty
// ---------------------------------------------------------------------------
__global__ void pack_kernel(float* __restrict__ out) {
    const size_t QOFF = (size_t)Bx * Dx * Tx;       // 4,194,304
    const size_t COFF = QOFF + (size_t)Sx * ROWS;   // + 262,144
    int i = blockIdx.x * 256 + threadIdx.x;
    if (i < Sx * ROWS) out[QOFF + i] = (float)g_codes[i];
    if (i == 0) {
        float ssum = 0.0f;
        for (int j = 0; j < Sx * GRID_STAGE; j++) ssum += g_part[j];
        out[COFF + 0] = 6000.0f;                                    // 8 * log2(1024) * 75
        out[COFF + 1] = ssum / ((float)Sx * (float)ROWS * (float)Dx);
    }
}

extern "C" void kernel_launch(void* const* d_in, const int* in_sizes, int n_in,
                              void* d_out, int out_size) {
    const float* x  = (const float*)d_in[0];
    const float* cb = (const float*)d_in[1];
    float* out = (float*)d_out;

    const int SMEM_BYTES = (128 * 132 + 16 * 132 + 2048 + 2048 + 128) * 4; // 92,928 B
    cudaFuncSetAttribute(stage_kernel, cudaFuncAttributeMaxDynamicSharedMemorySize, SMEM_BYTES);

    prep_transpose<<<dim3(Tx / 32, Dx / 32, Bx), dim3(32, 8)>>>(x);
    c2_kernel<<<(Sx * Kx * 32) / 256, 256>>>(cb);
    for (int s = 0; s < Sx; s++)
        stage_kernel<<<GRID_STAGE, 256, SMEM_BYTES>>>(cb, s);
    finish_transpose<<<dim3(Tx / 32, Dx / 32, Bx), dim3(32, 8)>>>(out);
    pack_kernel<<<(Sx * ROWS + 255) / 256, 256>>>(out);
}

// round 7
// speedup vs baseline: 2.3339x; 1.4428x over previous
#include <cuda_runtime.h>
#include <cuda_bf16.h>
#include <cstdint>

#define Bx 8
#define Dx 128
#define Tx 4096
#define Kx 1024
#define Sx 8
#define ROWS (Bx*Tx)            // 32768
#define NCTAS (ROWS/128)        // 256
#define RESCORE_THRESH 0.05f

// ---------------- device scratch (no runtime allocation) -------------------
__device__ float g_c2[Sx * Kx];                 // ||c||^2 fp32
__device__ float g_part[Sx * NCTAS];            // commit partials
// Packed B fragment images: per (stage, n, kc, tig) a 16B bundle:
//   {hi(k=kc*16+2tig, +1), hi(k=kc*16+8+2tig, +1), lo(pair0), lo(pair1)}
__device__ uint4 g_cbB[(size_t)Sx * Kx * 32];   // 4 MB

// ---------------- SMEM layout (byte offsets) --------------------------------
#define SMB_B    0            // 128 n-rows x 576B (padded)  = 73728
#define SMB_R    73728        // 128 x 132 fp32              = 67584
#define SMB_C2   141312       // 1024 fp32                   = 4096
#define SMB_IDX  145408       // 128 int                     = 512
#define SMB_RED  145920       // 256 fp32                    = 1024
#define SMB_T2V1 146944       // 128 fp32
#define SMB_T2I1 147456       // 128 int
#define SMB_T2V2 147968       // 128 fp32
#define SMB_T2I2 148480       // 128 int
#define SMEM_TOTAL 148992
#define BROW 576              // padded B row stride (bank-conflict-free)

// ---------------- helpers ----------------------------------------------------
__device__ __forceinline__ uint32_t pack_bf16(float a, float b) {
    __nv_bfloat162 h = __floats2bfloat162_rn(a, b);   // .x = a (low), .y = b (high)
    return *reinterpret_cast<uint32_t*>(&h);
}

// m16n8k16 row.col bf16 MMA, fp32 accumulate (in place)
__device__ __forceinline__ void mma_bf16(float* c, const uint32_t* a,
                                         uint32_t b0, uint32_t b1) {
    asm volatile(
        "mma.sync.aligned.m16n8k16.row.col.f32.bf16.bf16.f32 "
        "{%0,%1,%2,%3}, {%4,%5,%6,%7}, {%8,%9}, {%0,%1,%2,%3};"
        : "+f"(c[0]), "+f"(c[1]), "+f"(c[2]), "+f"(c[3])
        : "r"(a[0]), "r"(a[1]), "r"(a[2]), "r"(a[3]), "r"(b0), "r"(b1));
}

// top-2 merge with smaller-index tie-break
__device__ __forceinline__ void mrg(float& v1, int& i1, float& v2, int& i2,
                                    float v, int i) {
    if (v < v1 || (v == v1 && i < i1)) { v2 = v1; i2 = i1; v1 = v; i1 = i; }
    else if (v < v2 || (v == v2 && i < i2)) { v2 = v; i2 = i; }
}

// ---------------------------------------------------------------------------
// ||c||^2 for all stages: one warp per codeword.
// ---------------------------------------------------------------------------
__global__ void c2_kernel(const float* __restrict__ cb) {
    int w    = (blockIdx.x * blockDim.x + threadIdx.x) >> 5;
    int lane = threadIdx.x & 31;
    if (w >= Sx * Kx) return;
    float4 v = reinterpret_cast<const float4*>(cb)[(size_t)w * 32 + lane];
    float p = v.x * v.x + v.y * v.y + v.z * v.z + v.w * v.w;
    #pragma unroll
    for (int o = 16; o; o >>= 1) p += __shfl_down_sync(0xFFFFFFFFu, p, o);
    if (lane == 0) g_c2[w] = p;
}

// ---------------------------------------------------------------------------
// Codebooks -> split-bf16 fragment bundles. One thread per 16B bundle.
// idx = (s*Kx + n)*32 + kc*4 + tig
// ---------------------------------------------------------------------------
__global__ void cvt_cb_kernel(const float* __restrict__ cb) {
    int idx = blockIdx.x * 256 + threadIdx.x;
    if (idx >= Sx * Kx * 32) return;
    int tig = idx & 3;
    int kc  = (idx >> 2) & 7;
    int gk  = idx >> 5;                          // s*Kx + n
    const float* row = cb + (size_t)gk * Dx + kc * 16;
    float x0 = row[2 * tig],     x1 = row[2 * tig + 1];
    float x2 = row[8 + 2 * tig], x3 = row[8 + 2 * tig + 1];
    float h0 = __bfloat162float(__float2bfloat16(x0));
    float h1 = __bfloat162float(__float2bfloat16(x1));
    float h2 = __bfloat162float(__float2bfloat16(x2));
    float h3 = __bfloat162float(__float2bfloat16(x3));
    uint4 v;
    v.x = pack_bf16(h0, h1);
    v.y = pack_bf16(h2, h3);
    v.z = pack_bf16(x0 - h0, x1 - h1);
    v.w = pack_bf16(x2 - h2, x3 - h3);
    int s = gk >> 10;
    int n = gk & 1023;
    size_t dst = ((size_t)((s * 8 + (n >> 7)) * 128 + (n & 127))) * 32 + kc * 4 + tig;
    g_cbB[dst] = v;
}

// ---------------------------------------------------------------------------
// Fused 8-stage RVQ with mma.sync bf16 split GEMM.
// grid = 256 CTAs x 256 threads; each CTA owns 128 rows; warp w owns 16 rows.
// ---------------------------------------------------------------------------
__global__ void __launch_bounds__(256, 1)
rvq_kernel(const float* __restrict__ x, const float* __restrict__ cb,
           float* __restrict__ out) {
    extern __shared__ char sm[];
    float* R_sm = (float*)(sm + SMB_R);
    float* c2s  = (float*)(sm + SMB_C2);
    int*   sidx = (int*)(sm + SMB_IDX);
    float* red  = (float*)(sm + SMB_RED);
    float* t2v1 = (float*)(sm + SMB_T2V1);
    int*   t2i1 = (int*)(sm + SMB_T2I1);
    float* t2v2 = (float*)(sm + SMB_T2V2);
    int*   t2i2 = (int*)(sm + SMB_T2I2);

    const int tid  = threadIdx.x;
    const int wid  = tid >> 5;
    const int lane = tid & 31;
    const int g    = lane >> 2;       // group id 0..7
    const int tig  = lane & 3;        // thread-in-group
    const int wrow = wid * 16;        // warp's row base within CTA
    const int row0 = blockIdx.x * 128;
    const int b    = row0 >> 12;
    const int t0   = row0 & (Tx - 1);
    const size_t QOFF = (size_t)Bx * Dx * Tx;

    // ---- initial residual: R[t][d] = x[b][d][t0+t] (coalesced over t) ----
    #pragma unroll
    for (int it = 0; it < 64; it++) {
        int idx = it * 256 + tid;
        int d = idx >> 7, tl = idx & 127;
        R_sm[tl * 132 + d] = x[((size_t)b * Dx + d) * Tx + t0 + tl];
    }
    __syncthreads();

    for (int s = 0; s < Sx; s++) {
        // stage c2 into SMEM
        for (int i = tid; i < Kx; i += 256) c2s[i] = g_c2[s * Kx + i];

        // ---- A fragments for this warp's 16 rows (hi + lo), reused all nt ----
        uint32_t ah[8][4], al[8][4];
        #pragma unroll
        for (int kc = 0; kc < 8; kc++) {
            const float* base = &R_sm[(wrow + g) * 132 + kc * 16 + 2 * tig];
            float2 p0 = *(const float2*)(base);
            float2 p1 = *(const float2*)(base + 8 * 132);
            float2 p2 = *(const float2*)(base + 8);
            float2 p3 = *(const float2*)(base + 8 * 132 + 8);
            float h;
            h = __bfloat162float(__float2bfloat16(p0.x));
            float h0x = h;
            h = __bfloat162float(__float2bfloat16(p0.y));
            float h0y = h;
            h = __bfloat162float(__float2bfloat16(p1.x));
            float h1x = h;
            h = __bfloat162float(__float2bfloat16(p1.y));
            float h1y = h;
            h = __bfloat162float(__float2bfloat16(p2.x));
            float h2x = h;
            h = __bfloat162float(__float2bfloat16(p2.y));
            float h2y = h;
            h = __bfloat162float(__float2bfloat16(p3.x));
            float h3x = h;
            h = __bfloat162float(__float2bfloat16(p3.y));
            float h3y = h;
            ah[kc][0] = pack_bf16(h0x, h0y);
            ah[kc][1] = pack_bf16(h1x, h1y);
            ah[kc][2] = pack_bf16(h2x, h2y);
            ah[kc][3] = pack_bf16(h3x, h3y);
            al[kc][0] = pack_bf16(p0.x - h0x, p0.y - h0y);
            al[kc][1] = pack_bf16(p1.x - h1x, p1.y - h1y);
            al[kc][2] = pack_bf16(p2.x - h2x, p2.y - h2y);
            al[kc][3] = pack_bf16(p3.x - h3x, p3.y - h3y);
        }
        __syncthreads();   // c2s ready; previous nt-tile B consumers done

        // per-thread top-2: state a = row wrow+g, state b = row wrow+g+8
        const float INF = __int_as_float(0x7F800000);
        float v1a = INF, v2a = INF, v1b = INF, v2b = INF;
        int   i1a = 0x7fffffff, i2a = 0x7fffffff;
        int   i1b = 0x7fffffff, i2b = 0x7fffffff;

        for (int nt = 0; nt < 8; nt++) {
            // ---- stage B tile into padded SMEM (64KB payload) ----
            {
                const uint4* src = g_cbB + (size_t)(s * 8 + nt) * 128 * 32;
                #pragma unroll
                for (int it = 0; it < 16; it++) {
                    int idx = it * 256 + tid;
                    int r = idx >> 5, c = idx & 31;
                    *(uint4*)(sm + SMB_B + r * BROW + c * 16) = src[r * 32 + c];
                }
            }
            __syncthreads();

            float acc[64];
            #pragma unroll
            for (int i = 0; i < 64; i++) acc[i] = 0.0f;

            #pragma unroll
            for (int kc = 0; kc < 8; kc++) {
                #pragma unroll
                for (int nb = 0; nb < 16; nb++) {
                    uint4 bv = *(const uint4*)(sm + SMB_B + (nb * 8 + g) * BROW
                                               + kc * 64 + tig * 16);
                    mma_bf16(&acc[nb * 4], ah[kc], bv.x, bv.y);   // hi*hi
                    mma_bf16(&acc[nb * 4], ah[kc], bv.z, bv.w);   // hi*lo
                    mma_bf16(&acc[nb * 4], al[kc], bv.x, bv.y);   // lo*hi
                }
            }

            // ---- fold distances into per-thread top-2 ----
            #pragma unroll
            for (int nb = 0; nb < 16; nb++) {
                int n0 = nt * 128 + nb * 8 + 2 * tig;
                float2 cc = *(const float2*)&c2s[n0];
                float d0 = fmaf(-2.0f, acc[nb * 4 + 0], cc.x);
                float d1 = fmaf(-2.0f, acc[nb * 4 + 1], cc.y);
                float d2 = fmaf(-2.0f, acc[nb * 4 + 2], cc.x);
                float d3 = fmaf(-2.0f, acc[nb * 4 + 3], cc.y);
                if (d0 < v1a) { v2a = v1a; i2a = i1a; v1a = d0; i1a = n0; }
                else if (d0 < v2a) { v2a = d0; i2a = n0; }
                if (d1 < v1a) { v2a = v1a; i2a = i1a; v1a = d1; i1a = n0 + 1; }
                else if (d1 < v2a) { v2a = d1; i2a = n0 + 1; }
                if (d2 < v1b) { v2b = v1b; i2b = i1b; v1b = d2; i1b = n0; }
                else if (d2 < v2b) { v2b = d2; i2b = n0; }
                if (d3 < v1b) { v2b = v1b; i2b = i1b; v1b = d3; i1b = n0 + 1; }
                else if (d3 < v2b) { v2b = d3; i2b = n0 + 1; }
            }
            __syncthreads();   // B tile safe to overwrite next nt
        }

        // ---- reduce top-2 across the 4 tig lanes (quads) ----
        #pragma unroll
        for (int off = 1; off <= 2; off <<= 1) {
            float w1 = __shfl_xor_sync(0xFFFFFFFFu, v1a, off);
            int   j1 = __shfl_xor_sync(0xFFFFFFFFu, i1a, off);
            float w2 = __shfl_xor_sync(0xFFFFFFFFu, v2a, off);
            int   j2 = __shfl_xor_sync(0xFFFFFFFFu, i2a, off);
            mrg(v1a, i1a, v2a, i2a, w1, j1);
            mrg(v1a, i1a, v2a, i2a, w2, j2);
            w1 = __shfl_xor_sync(0xFFFFFFFFu, v1b, off);
            j1 = __shfl_xor_sync(0xFFFFFFFFu, i1b, off);
            w2 = __shfl_xor_sync(0xFFFFFFFFu, v2b, off);
            j2 = __shfl_xor_sync(0xFFFFFFFFu, i2b, off);
            mrg(v1b, i1b, v2b, i2b, w1, j1);
            mrg(v1b, i1b, v2b, i2b, w2, j2);
        }
        if (tig == 0) {
            t2v1[wrow + g] = v1a; t2i1[wrow + g] = i1a;
            t2v2[wrow + g] = v2a; t2i2[wrow + g] = i2a;
            t2v1[wrow + g + 8] = v1b; t2i1[wrow + g + 8] = i1b;
            t2v2[wrow + g + 8] = v2b; t2i2[wrow + g + 8] = i2b;
        }
        __syncthreads();

        // ---- pick; rescore near-ties exactly in fp32 ----
        if (tid < 128) {
            float pv1 = t2v1[tid], pv2 = t2v2[tid];
            int   pi1 = t2i1[tid], pi2 = t2i2[tid];
            int bi = pi1;
            if (pv2 - pv1 < RESCORE_THRESH) {
                const float* rr  = &R_sm[tid * 132];
                const float* c1p = cb + ((size_t)s * Kx + pi1) * Dx;
                const float* c2p = cb + ((size_t)s * Kx + pi2) * Dx;
                float dot1 = 0.f, cc1 = 0.f, dot2 = 0.f, cc2 = 0.f;
                #pragma unroll 8
                for (int i = 0; i < Dx; i++) {
                    float r = rr[i], a = c1p[i], e = c2p[i];
                    dot1 = fmaf(r, a, dot1); cc1 = fmaf(a, a, cc1);
                    dot2 = fmaf(r, e, dot2); cc2 = fmaf(e, e, cc2);
                }
                float d1 = fmaf(-2.0f, dot1, cc1);
                float d2 = fmaf(-2.0f, dot2, cc2);
                if (d2 < d1 || (d2 == d1 && pi2 < pi1)) bi = pi2;
            }
            sidx[tid] = bi;
            out[QOFF + (size_t)s * ROWS + row0 + tid] = (float)bi;
        }
        __syncthreads();

        // ---- residual update + commit partial ----
        float cm = 0.0f;
        #pragma unroll
        for (int it = 0; it < 64; it++) {
            int idx = it * 256 + tid;
            int m = idx >> 7, d = idx & 127;
            int k = sidx[m];
            float q  = cb[((size_t)s * Kx + k) * Dx + d];
            float r  = R_sm[m * 132 + d];
            float nr = r - q;
            cm = fmaf(nr, nr, cm);
            R_sm[m * 132 + d] = nr;
        }
        red[tid] = cm;
        __syncthreads();
        #pragma unroll
        for (int st = 128; st > 0; st >>= 1) {
            if (tid < st) red[tid] += red[tid + st];
            __syncthreads();
        }
        if (tid == 0) g_part[s * NCTAS + blockIdx.x] = red[0];
        __syncthreads();
    }

    // ---- quantized output: out[b][d][t] = x - R_final ----
    #pragma unroll
    for (int it = 0; it < 64; it++) {
        int idx = it * 256 + tid;
        int d = idx >> 7, tl = idx & 127;
        size_t go = ((size_t)b * Dx + d) * Tx + t0 + tl;
        out[go] = x[go] - R_sm[tl * 132 + d];
    }
}

// ---------------------------------------------------------------------------
// bw + penalty
// ---------------------------------------------------------------------------
__global__ void pack_kernel(float* __restrict__ out) {
    __shared__ float red[256];
    const size_t COFF = (size_t)Bx * Dx * Tx + (size_t)Sx * ROWS;
    int tid = threadIdx.x;
    float s = 0.0f;
    for (int i = tid; i < Sx * NCTAS; i += 256) s += g_part[i];
    red[tid] = s;
    __syncthreads();
    #pragma unroll
    for (int st = 128; st > 0; st >>= 1) {
        if (tid < st) red[tid] += red[tid + st];
        __syncthreads();
    }
    if (tid == 0) {
        out[COFF + 0] = 6000.0f;   // 8 * log2(1024) * 75
        out[COFF + 1] = red[0] / ((float)Sx * (float)ROWS * (float)Dx);
    }
}

extern "C" void kernel_launch(void* const* d_in, const int* in_sizes, int n_in,
                              void* d_out, int out_size) {
    const float* x  = (const float*)d_in[0];
    const float* cb = (const float*)d_in[1];
    float* out = (float*)d_out;

    cudaFuncSetAttribute(rvq_kernel, cudaFuncAttributeMaxDynamicSharedMemorySize,
                         SMEM_TOTAL);

    c2_kernel<<<(Sx * Kx * 32) / 256, 256>>>(cb);
    cvt_cb_kernel<<<(Sx * Kx * 32) / 256, 256>>>(cb);
    rvq_kernel<<<NCTAS, 256, SMEM_TOTAL>>>(x, cb, out);
    pack_kernel<<<1, 256>>>(out);
}